// round 1
// baseline (speedup 1.0000x reference)
#include <cuda_runtime.h>

#define B_    4
#define C_    256
#define H_    80
#define W_    80
#define HW    6400
#define K2    9
#define KDIM  2304     // C_ * K2
#define COUT  256

// ---------------- scratch (device globals; no allocation allowed) ----------
__device__ float  g_xnhwc[B_ * HW * C_];        // x transposed to NHWC (26.2 MB)
__device__ float  g_wT[KDIM * COUT];            // conv_w transposed [c*9+k][o]
__device__ float  g_owT[KDIM * 20];             // offset_w transposed [c*9+nb][20] (18 padded to 20)
__device__ float4 g_twgt[B_ * K2 * HW];         // per (b,k,pixel): 4 bilinear weights * validity
__device__ int4   g_tidx[B_ * K2 * HW];         // per (b,k,pixel): 4 clamped NHWC element bases ((y*W+x)*C)

// ---------------- kernel 1: NCHW -> NHWC transpose -------------------------
__global__ void k_transpose(const float* __restrict__ x) {
    __shared__ float tile[32][33];
    int b   = blockIdx.z;
    int hw0 = blockIdx.x * 32;
    int c0  = blockIdx.y * 32;
    int tx = threadIdx.x, ty = threadIdx.y;      // 32 x 8
    const float* xb = x + b * C_ * HW;
    #pragma unroll
    for (int i = 0; i < 32; i += 8)
        tile[ty + i][tx] = xb[(c0 + ty + i) * HW + hw0 + tx];
    __syncthreads();
    float* ob = g_xnhwc + b * HW * C_;
    #pragma unroll
    for (int i = 0; i < 32; i += 8)
        ob[(hw0 + ty + i) * C_ + c0 + tx] = tile[tx][ty + i];
}

// ---------------- kernel 2a/2b: weight transposes --------------------------
__global__ void k_wt(const float* __restrict__ cw) {
    int idx = blockIdx.x * 256 + threadIdx.x;    // 2304*256 elements
    if (idx < KDIM * COUT) {
        int row = idx >> 8;    // kflat = c*9+k
        int o   = idx & 255;
        g_wT[idx] = __ldg(cw + o * KDIM + row);
    }
}

__global__ void k_owt(const float* __restrict__ ow) {
    int idx = blockIdx.x * 256 + threadIdx.x;    // 2304*20 elements
    if (idx < KDIM * 20) {
        int row = idx / 20, oc = idx % 20;
        g_owT[idx] = (oc < 18) ? __ldg(ow + oc * KDIM + row) : 0.f;
    }
}

// ---------------- kernel 3: offset conv (3x3, 256->18) + tap metadata ------
// Block: 256 threads = 8 warps. 32 pixels per block; each warp handles a
// 32-channel chunk of the K reduction (lane-per-pixel, coalesced NCHW loads).
__global__ void __launch_bounds__(256) k_offset(const float* __restrict__ x,
                                                const float* __restrict__ off_b) {
    __shared__ float red[8][32][18];
    __shared__ float offs[32][18];

    int pg   = blockIdx.x;                 // 0..799
    int b    = pg / (HW / 32);
    int hw0  = (pg % (HW / 32)) * 32;
    int lane = threadIdx.x & 31;
    int wq   = threadIdx.x >> 5;           // channel chunk 0..7
    int p    = hw0 + lane;
    int py   = p / W_, px = p % W_;

    int noff[9];
    #pragma unroll
    for (int nb = 0; nb < 9; nb++) {
        int ny = py + nb / 3 - 1, nx = px + nb % 3 - 1;
        noff[nb] = (ny >= 0 && ny < H_ && nx >= 0 && nx < W_) ? ny * W_ + nx : -1;
    }

    float acc[18];
    #pragma unroll
    for (int i = 0; i < 18; i++) acc[i] = 0.f;

    int c0 = wq * 32;
    const float* xb = x + (size_t)(b * C_ + c0) * HW;
    for (int c = 0; c < 32; c++) {
        const float* xc = xb + c * HW;
        const float4* wr = (const float4*)(g_owT + (size_t)(c0 + c) * 9 * 20);
        #pragma unroll
        for (int nb = 0; nb < 9; nb++) {
            float xv = (noff[nb] >= 0) ? __ldg(xc + noff[nb]) : 0.f;
            const float4* w = wr + nb * 5;
            float wv[20];
            *(float4*)&wv[0]  = __ldg(w + 0);
            *(float4*)&wv[4]  = __ldg(w + 1);
            *(float4*)&wv[8]  = __ldg(w + 2);
            *(float4*)&wv[12] = __ldg(w + 3);
            *(float4*)&wv[16] = __ldg(w + 4);
            #pragma unroll
            for (int i = 0; i < 18; i++) acc[i] = fmaf(xv, wv[i], acc[i]);
        }
    }

    #pragma unroll
    for (int i = 0; i < 18; i++) red[wq][lane][i] = acc[i];
    __syncthreads();

    for (int u = threadIdx.x; u < 32 * 18; u += 256) {
        int l = u / 18, oc = u % 18;
        float s = 0.f;
        #pragma unroll
        for (int q = 0; q < 8; q++) s += red[q][l][oc];
        offs[l][oc] = s + __ldg(off_b + oc);
    }
    __syncthreads();

    // tap metadata per (pixel, k)
    for (int u = threadIdx.x; u < 32 * 9; u += 256) {
        int l = u / 9, k = u % 9;
        float dy = offs[l][2 * k], dx = offs[l][2 * k + 1];
        int pp = hw0 + l;
        int yy = pp / W_, xx = pp % W_;
        float fy = (float)(yy + k / 3 - 1) + dy;
        float fx = (float)(xx + k % 3 - 1) + dx;
        float y0f = floorf(fy), x0f = floorf(fx);
        float wy = fy - y0f, wx = fx - x0f;
        int y0 = (int)y0f, x0 = (int)x0f;
        int y1 = y0 + 1,   x1 = x0 + 1;
        float vy0 = (y0 >= 0 && y0 < H_) ? 1.f : 0.f;
        float vy1 = (y1 >= 0 && y1 < H_) ? 1.f : 0.f;
        float vx0 = (x0 >= 0 && x0 < W_) ? 1.f : 0.f;
        float vx1 = (x1 >= 0 && x1 < W_) ? 1.f : 0.f;
        int cy0 = min(max(y0, 0), H_ - 1), cy1 = min(max(y1, 0), H_ - 1);
        int cx0 = min(max(x0, 0), W_ - 1), cx1 = min(max(x1, 0), W_ - 1);
        float4 wt;
        wt.x = (1.f - wy) * (1.f - wx) * vy0 * vx0;
        wt.y = (1.f - wy) * wx         * vy0 * vx1;
        wt.z = wy * (1.f - wx)         * vy1 * vx0;
        wt.w = wy * wx                 * vy1 * vx1;
        int4 id;
        id.x = (cy0 * W_ + cx0) * C_;
        id.y = (cy0 * W_ + cx1) * C_;
        id.z = (cy1 * W_ + cx0) * C_;
        id.w = (cy1 * W_ + cx1) * C_;
        int m = (b * 9 + k) * HW + pp;
        g_twgt[m] = wt;
        g_tidx[m] = id;
    }
}

// ---------------- kernel 4: main deformable GEMM ---------------------------
// M=256 (2 m-blocks of 128), N=25600 (200 n-blocks of 128), K=2304 in
// chunks of 144 (16 channels x 9 taps). im2col (bilinear gather) into SMEM,
// then 8x8-register-tile FFMA GEMM.
#define BM 128
#define BN 128
#define KC 16
#define KK (KC * K2)   // 144

__global__ void __launch_bounds__(256, 1) k_main(const float* __restrict__ cb,
                                                 float* __restrict__ out) {
    extern __shared__ float smem[];
    float* w_s = smem;             // [KK][BM]
    float* v_s = smem + KK * BM;   // [KK][BN]

    int nb   = blockIdx.x;         // 400
    int mblk = nb & 1;
    int nblk = nb >> 1;            // 0..199
    int b    = nblk / (HW / BN);
    int hw0  = (nblk % (HW / BN)) * BN;
    int o0   = mblk * BM;
    int tid  = threadIdx.x;
    int tx   = tid & 15;           // output-channel group
    int ty   = tid >> 4;           // pixel group

    float acc[8][8];
    #pragma unroll
    for (int i = 0; i < 8; i++)
        #pragma unroll
        for (int j = 0; j < 8; j++) acc[i][j] = 0.f;

    const float4* xb4 = (const float4*)(g_xnhwc + (size_t)b * HW * C_);
    int b9 = b * 9;

    for (int ch = 0; ch < C_; ch += KC) {
        // --- load weight chunk [KK][BM] (coalesced rows) ---
        {
            int r   = tid >> 5;            // 0..7
            int col = (tid & 31) * 4;
            #pragma unroll
            for (int rr = r; rr < KK; rr += 8)
                *(float4*)&w_s[rr * BM + col] =
                    *(const float4*)&g_wT[(size_t)(ch * 9 + rr) * COUT + o0 + col];
        }
        // --- im2col: bilinear gather 16 channels x 9 taps x 128 pixels ---
        for (int u = tid; u < BN * 9; u += 256) {
            int p = u & (BN - 1);
            int k = u >> 7;
            int m = (b9 + k) * HW + hw0 + p;
            float4 wt = g_twgt[m];
            int4  id  = g_tidx[m];
            int i0 = (id.x + ch) >> 2;
            int i1 = (id.y + ch) >> 2;
            int i2 = (id.z + ch) >> 2;
            int i3 = (id.w + ch) >> 2;
            #pragma unroll
            for (int cc = 0; cc < 4; cc++) {
                float4 t0 = __ldg(xb4 + i0 + cc);
                float4 t1 = __ldg(xb4 + i1 + cc);
                float4 t2 = __ldg(xb4 + i2 + cc);
                float4 t3 = __ldg(xb4 + i3 + cc);
                float4 r;
                r.x = wt.x * t0.x + wt.y * t1.x + wt.z * t2.x + wt.w * t3.x;
                r.y = wt.x * t0.y + wt.y * t1.y + wt.z * t2.y + wt.w * t3.y;
                r.z = wt.x * t0.z + wt.y * t1.z + wt.z * t2.z + wt.w * t3.z;
                r.w = wt.x * t0.w + wt.y * t1.w + wt.z * t2.w + wt.w * t3.w;
                int cl = cc * 4;
                v_s[((cl + 0) * 9 + k) * BN + p] = r.x;
                v_s[((cl + 1) * 9 + k) * BN + p] = r.y;
                v_s[((cl + 2) * 9 + k) * BN + p] = r.z;
                v_s[((cl + 3) * 9 + k) * BN + p] = r.w;
            }
        }
        __syncthreads();

        // --- FFMA GEMM over this K chunk ---
        #pragma unroll 4
        for (int kk = 0; kk < KK; kk++) {
            float4 a0 = *(float4*)&w_s[kk * BM + tx * 8];
            float4 a1 = *(float4*)&w_s[kk * BM + tx * 8 + 4];
            float4 b0 = *(float4*)&v_s[kk * BN + ty * 8];
            float4 b1 = *(float4*)&v_s[kk * BN + ty * 8 + 4];
            float av[8] = {a0.x, a0.y, a0.z, a0.w, a1.x, a1.y, a1.z, a1.w};
            float bv[8] = {b0.x, b0.y, b0.z, b0.w, b1.x, b1.y, b1.z, b1.w};
            #pragma unroll
            for (int i = 0; i < 8; i++)
                #pragma unroll
                for (int j = 0; j < 8; j++)
                    acc[i][j] = fmaf(av[i], bv[j], acc[i][j]);
        }
        __syncthreads();
    }

    // --- epilogue: bias + NCHW store ---
    #pragma unroll
    for (int i = 0; i < 8; i++) {
        int o = o0 + tx * 8 + i;
        float bias = __ldg(cb + o);
        float* orow = out + (size_t)(b * COUT + o) * HW + hw0 + ty * 8;
        float4 s0, s1;
        s0.x = acc[i][0] + bias; s0.y = acc[i][1] + bias;
        s0.z = acc[i][2] + bias; s0.w = acc[i][3] + bias;
        s1.x = acc[i][4] + bias; s1.y = acc[i][5] + bias;
        s1.z = acc[i][6] + bias; s1.w = acc[i][7] + bias;
        *(float4*)orow = s0;
        *(float4*)(orow + 4) = s1;
    }
}

// ---------------- launch -----------------------------------------------------
extern "C" void kernel_launch(void* const* d_in, const int* in_sizes, int n_in,
                              void* d_out, int out_size) {
    const float* x    = (const float*)d_in[0];   // (4,256,80,80)
    const float* ow   = (const float*)d_in[1];   // (18,256,3,3)
    const float* ob   = (const float*)d_in[2];   // (18,)
    const float* cw   = (const float*)d_in[3];   // (256,256,3,3)
    const float* cb   = (const float*)d_in[4];   // (256,)
    float* out        = (float*)d_out;           // (4,256,80,80)

    static int smem_set = 0;
    // idempotent; executes immediately (not a captured op)
    cudaFuncSetAttribute(k_main, cudaFuncAttributeMaxDynamicSharedMemorySize,
                         (KK * BM + KK * BN) * (int)sizeof(float));
    (void)smem_set;

    // independent prep kernels
    {
        dim3 grid(HW / 32, C_ / 32, B_);
        dim3 block(32, 8);
        k_transpose<<<grid, block>>>(x);
    }
    k_wt<<<(KDIM * COUT + 255) / 256, 256>>>(cw);
    k_owt<<<(KDIM * 20 + 255) / 256, 256>>>(ow);
    k_offset<<<B_ * HW / 32, 256>>>(x, ob);

    // main deformable GEMM
    k_main<<<400, 256, (KK * BM + KK * BN) * (int)sizeof(float)>>>(cb, out);
}

// round 4
// speedup vs baseline: 1.8129x; 1.8129x over previous
#include <cuda_runtime.h>
#include <cuda_bf16.h>
#include <cstdint>

#define B_    4
#define C_    256
#define H_    80
#define W_    80
#define HW    6400
#define K2    9
#define KDIM  2304
#define COUT  256
#define NCHUNK 72          // 9 taps * 8 channel-groups of 32

// ---------------- device scratch ----------------
__device__ float  g_xnhwc[B_ * HW * C_];          // x in NHWC
__device__ float  g_owT[KDIM * 20];               // offset weights transposed (18->20 pad)
__device__ uint4  g_wA[NCHUNK * 2 * 16 * 2 * 32]; // fragment-packed bf16 weights (hi/lo)
__device__ float4 g_twgt[B_ * K2 * HW];           // bilinear weights * validity
__device__ int4   g_tidx[B_ * K2 * HW];           // clamped NHWC bases

// ---------------- mma helper ----------------
__device__ __forceinline__ void mma16816(float* d, const uint32_t* a, const uint32_t* b) {
    asm volatile(
        "mma.sync.aligned.m16n8k16.row.col.f32.bf16.bf16.f32 "
        "{%0,%1,%2,%3}, {%4,%5,%6,%7}, {%8,%9}, {%0,%1,%2,%3};"
        : "+f"(d[0]), "+f"(d[1]), "+f"(d[2]), "+f"(d[3])
        : "r"(a[0]), "r"(a[1]), "r"(a[2]), "r"(a[3]), "r"(b[0]), "r"(b[1]));
}

__device__ __forceinline__ uint32_t pack_bf16(float lo_v, float hi_v) {
    __nv_bfloat162 h;
    h.x = __float2bfloat16(lo_v);
    h.y = __float2bfloat16(hi_v);
    return *(uint32_t*)&h;
}

// ---------------- kernel 1: NCHW -> NHWC transpose -------------------------
__global__ void k_transpose(const float* __restrict__ x) {
    __shared__ float tile[32][33];
    int b   = blockIdx.z;
    int hw0 = blockIdx.x * 32;
    int c0  = blockIdx.y * 32;
    int tx = threadIdx.x, ty = threadIdx.y;
    const float* xb = x + b * C_ * HW;
    #pragma unroll
    for (int i = 0; i < 32; i += 8)
        tile[ty + i][tx] = xb[(c0 + ty + i) * HW + hw0 + tx];
    __syncthreads();
    float* ob = g_xnhwc + b * HW * C_;
    #pragma unroll
    for (int i = 0; i < 32; i += 8)
        ob[(hw0 + ty + i) * C_ + c0 + tx] = tile[tx][ty + i];
}

// ---------------- kernel 2: offset-weight transpose ------------------------
__global__ void k_owt(const float* __restrict__ ow) {
    int idx = blockIdx.x * 256 + threadIdx.x;
    if (idx < KDIM * 20) {
        int row = idx / 20, oc = idx % 20;
        g_owT[idx] = (oc < 18) ? __ldg(ow + oc * KDIM + row) : 0.f;
    }
}

// ---------------- kernel 3: conv-weight split into mma fragment order ------
// g_wA index: ((((q*2 + term)*16 + mt)*2 + s)*32 + lane), each uint4 = the 4
// A-fragment regs for that lane of an m16n8k16 bf16 mma.
__global__ void k_wprep(const float* __restrict__ cw) {
    int e = blockIdx.x * 256 + threadIdx.x;
    if (e >= NCHUNK * 2 * 16 * 2 * 32) return;
    int lane = e & 31;
    int s    = (e >> 5) & 1;
    int mt   = (e >> 6) & 15;
    int term = (e >> 10) & 1;
    int q    = e >> 11;
    int tap   = q >> 3;
    int cbase = (q & 7) * 32;
    uint32_t r[4];
    #pragma unroll
    for (int rr = 0; rr < 4; rr++) {
        int m  = mt * 16 + (lane >> 2) + ((rr & 1) << 3);
        int kl = s * 16 + (lane & 3) * 2 + ((rr >> 1) << 3);
        float w0 = __ldg(cw + m * KDIM + (cbase + kl) * 9 + tap);
        float w1 = __ldg(cw + m * KDIM + (cbase + kl + 1) * 9 + tap);
        if (term) {
            w0 -= __bfloat162float(__float2bfloat16(w0));
            w1 -= __bfloat162float(__float2bfloat16(w1));
        }
        r[rr] = pack_bf16(w0, w1);
    }
    g_wA[e] = make_uint4(r[0], r[1], r[2], r[3]);
}

// ---------------- kernel 4: offset conv + tap metadata (2 px/lane) ---------
__global__ void __launch_bounds__(256) k_offset(const float* __restrict__ x,
                                                const float* __restrict__ off_b) {
    __shared__ float red[8][64][18];
    __shared__ float offs[64][18];

    int pg   = blockIdx.x;                 // 0..399
    int b    = pg / (HW / 64);
    int hw0  = (pg % (HW / 64)) * 64;
    int lane = threadIdx.x & 31;
    int wq   = threadIdx.x >> 5;

    int p0 = hw0 + lane, p1 = p0 + 32;
    int noff0[9], noff1[9];
    {
        int y0 = p0 / W_, x0 = p0 % W_;
        int y1 = p1 / W_, x1 = p1 % W_;
        #pragma unroll
        for (int nb = 0; nb < 9; nb++) {
            int dy = nb / 3 - 1, dx = nb % 3 - 1;
            int ay = y0 + dy, ax = x0 + dx;
            noff0[nb] = (ay >= 0 && ay < H_ && ax >= 0 && ax < W_) ? ay * W_ + ax : -1;
            int by = y1 + dy, bx = x1 + dx;
            noff1[nb] = (by >= 0 && by < H_ && bx >= 0 && bx < W_) ? by * W_ + bx : -1;
        }
    }

    float acc0[18], acc1[18];
    #pragma unroll
    for (int i = 0; i < 18; i++) { acc0[i] = 0.f; acc1[i] = 0.f; }

    int c0 = wq * 32;
    const float* xb = x + (size_t)(b * C_ + c0) * HW;
    for (int c = 0; c < 32; c++) {
        const float* xc = xb + c * HW;
        const float4* wr = (const float4*)(g_owT + (size_t)(c0 + c) * 180);
        #pragma unroll
        for (int nb = 0; nb < 9; nb++) {
            float xv0 = (noff0[nb] >= 0) ? __ldg(xc + noff0[nb]) : 0.f;
            float xv1 = (noff1[nb] >= 0) ? __ldg(xc + noff1[nb]) : 0.f;
            const float4* w = wr + nb * 5;
            float wv[20];
            *(float4*)&wv[0]  = __ldg(w + 0);
            *(float4*)&wv[4]  = __ldg(w + 1);
            *(float4*)&wv[8]  = __ldg(w + 2);
            *(float4*)&wv[12] = __ldg(w + 3);
            *(float4*)&wv[16] = __ldg(w + 4);
            #pragma unroll
            for (int i = 0; i < 18; i++) {
                acc0[i] = fmaf(xv0, wv[i], acc0[i]);
                acc1[i] = fmaf(xv1, wv[i], acc1[i]);
            }
        }
    }

    #pragma unroll
    for (int i = 0; i < 18; i++) {
        red[wq][lane][i]      = acc0[i];
        red[wq][lane + 32][i] = acc1[i];
    }
    __syncthreads();

    for (int u = threadIdx.x; u < 64 * 18; u += 256) {
        int l = u / 18, oc = u % 18;
        float s = 0.f;
        #pragma unroll
        for (int qx = 0; qx < 8; qx++) s += red[qx][l][oc];
        offs[l][oc] = s + __ldg(off_b + oc);
    }
    __syncthreads();

    for (int u = threadIdx.x; u < 64 * 9; u += 256) {
        int l = u / 9, k = u % 9;
        float dy = offs[l][2 * k], dx = offs[l][2 * k + 1];
        int pp = hw0 + l;
        int yy = pp / W_, xx = pp % W_;
        float fy = (float)(yy + k / 3 - 1) + dy;
        float fx = (float)(xx + k % 3 - 1) + dx;
        float y0f = floorf(fy), x0f = floorf(fx);
        float wy = fy - y0f, wx = fx - x0f;
        int y0 = (int)y0f, x0 = (int)x0f;
        int y1 = y0 + 1,   x1 = x0 + 1;
        float vy0 = (y0 >= 0 && y0 < H_) ? 1.f : 0.f;
        float vy1 = (y1 >= 0 && y1 < H_) ? 1.f : 0.f;
        float vx0 = (x0 >= 0 && x0 < W_) ? 1.f : 0.f;
        float vx1 = (x1 >= 0 && x1 < W_) ? 1.f : 0.f;
        int cy0 = min(max(y0, 0), H_ - 1), cy1 = min(max(y1, 0), H_ - 1);
        int cx0 = min(max(x0, 0), W_ - 1), cx1 = min(max(x1, 0), W_ - 1);
        float4 wt;
        wt.x = (1.f - wy) * (1.f - wx) * vy0 * vx0;
        wt.y = (1.f - wy) * wx         * vy0 * vx1;
        wt.z = wy * (1.f - wx)         * vy1 * vx0;
        wt.w = wy * wx                 * vy1 * vx1;
        int4 id;
        id.x = (cy0 * W_ + cx0) * C_;
        id.y = (cy0 * W_ + cx1) * C_;
        id.z = (cy1 * W_ + cx0) * C_;
        id.w = (cy1 * W_ + cx1) * C_;
        int m = (b * 9 + k) * HW + pp;
        g_twgt[m] = wt;
        g_tidx[m] = id;
    }
}

// ---------------- kernel 5: main GEMM via mma.sync bf16 split --------------
// Block: 128 M x 128 N, 256 threads (8 warps = 2 Mwarp x 4 Nwarp, warp tile
// 64x32). K = 2304 in 72 chunks of 32 (1 tap x 32 ch). B gathered+split into
// SMEM (80 B pixel stride); A loaded fragment-packed from global.
// 2 CTAs/SM alternate gather and MMA phases.
#define BROW 20    // u32 words per pixel row in sB

__global__ void __launch_bounds__(256, 2) k_main(const float* __restrict__ cb,
                                                 float* __restrict__ out) {
    __shared__ uint32_t sB[2][128 * BROW];   // [term][pixel*20 + word]

    int tid  = threadIdx.x;
    int wid  = tid >> 5, lane = tid & 31;
    int mb   = blockIdx.x & 1;
    int nblk = blockIdx.x >> 1;              // 0..199 (4 batches x 50 tiles)
    int b    = nblk / (HW / 128);
    int hw0  = (nblk % (HW / 128)) * 128;
    int wm   = wid >> 2, wn = wid & 3;

    float acc[4][4][4];
    #pragma unroll
    for (int i = 0; i < 4; i++)
        #pragma unroll
        for (int j = 0; j < 4; j++)
            #pragma unroll
            for (int r = 0; r < 4; r++) acc[i][j][r] = 0.f;

    const float4* xb4 = (const float4*)(g_xnhwc + (size_t)b * HW * C_);
    int b9 = b * 9;
    int p = tid >> 1, half = tid & 1;
    int mtbase = mb * 8 + wm * 4;

    for (int q = 0; q < NCHUNK; q++) {
        int tap = q >> 3, cg = q & 7;
        int mm = (b9 + tap) * HW + hw0 + p;
        float4 wt = g_twgt[mm];
        int4  id  = g_tidx[mm];

        __syncthreads();   // previous chunk's mma done -> safe to overwrite sB

        #pragma unroll
        for (int qq = 0; qq < 4; qq++) {
            int c = cg * 32 + half * 16 + qq * 4;
            float4 t0 = __ldg(xb4 + ((id.x + c) >> 2));
            float4 t1 = __ldg(xb4 + ((id.y + c) >> 2));
            float4 t2 = __ldg(xb4 + ((id.z + c) >> 2));
            float4 t3 = __ldg(xb4 + ((id.w + c) >> 2));
            float4 v;
            v.x = wt.x * t0.x + wt.y * t1.x + wt.z * t2.x + wt.w * t3.x;
            v.y = wt.x * t0.y + wt.y * t1.y + wt.z * t2.y + wt.w * t3.y;
            v.z = wt.x * t0.z + wt.y * t1.z + wt.z * t2.z + wt.w * t3.z;
            v.w = wt.x * t0.w + wt.y * t1.w + wt.z * t2.w + wt.w * t3.w;
            // hi terms
            uint32_t h01 = pack_bf16(v.x, v.y);
            uint32_t h23 = pack_bf16(v.z, v.w);
            // lo residuals
            __nv_bfloat162 hh01 = *(__nv_bfloat162*)&h01;
            __nv_bfloat162 hh23 = *(__nv_bfloat162*)&h23;
            float lx = v.x - __bfloat162float(hh01.x);
            float ly = v.y - __bfloat162float(hh01.y);
            float lz = v.z - __bfloat162float(hh23.x);
            float lw = v.w - __bfloat162float(hh23.y);
            uint32_t l01 = pack_bf16(lx, ly);
            uint32_t l23 = pack_bf16(lz, lw);
            int word = p * BROW + half * 8 + qq * 2;
            *(uint2*)&sB[0][word] = make_uint2(h01, h23);
            *(uint2*)&sB[1][word] = make_uint2(l01, l23);
        }
        __syncthreads();

        // ---- mma phase ----
        #pragma unroll
        for (int s = 0; s < 2; s++) {
            uint32_t Bh[4][2], Bl[4][2];
            #pragma unroll
            for (int j = 0; j < 4; j++) {
                int pr = wn * 32 + j * 8 + (lane >> 2);
                int w  = pr * BROW + s * 8 + (lane & 3);
                Bh[j][0] = sB[0][w];
                Bh[j][1] = sB[0][w + 4];
                Bl[j][0] = sB[1][w];
                Bl[j][1] = sB[1][w + 4];
            }
            uint4 Ah[4];
            #pragma unroll
            for (int i = 0; i < 4; i++)
                Ah[i] = __ldg(&g_wA[(((q * 2 + 0) * 16 + mtbase + i) * 2 + s) * 32 + lane]);
            #pragma unroll
            for (int i = 0; i < 4; i++)
                #pragma unroll
                for (int j = 0; j < 4; j++)
                    mma16816(acc[i][j], (const uint32_t*)&Ah[i], Bh[j]);
            #pragma unroll
            for (int i = 0; i < 4; i++)
                #pragma unroll
                for (int j = 0; j < 4; j++)
                    mma16816(acc[i][j], (const uint32_t*)&Ah[i], Bl[j]);
            #pragma unroll
            for (int i = 0; i < 4; i++) {
                uint4 Al = __ldg(&g_wA[(((q * 2 + 1) * 16 + mtbase + i) * 2 + s) * 32 + lane]);
                #pragma unroll
                for (int j = 0; j < 4; j++)
                    mma16816(acc[i][j], (const uint32_t*)&Al, Bh[j]);
            }
        }
    }

    // ---- epilogue: bias + NCHW store ----
    int q_ = lane >> 2, t = lane & 3;
    #pragma unroll
    for (int i = 0; i < 4; i++) {
        int o0 = mb * 128 + wm * 64 + i * 16 + q_;
        float bias0 = __ldg(cb + o0);
        float bias1 = __ldg(cb + o0 + 8);
        float* r0 = out + (size_t)(b * COUT + o0) * HW + hw0 + wn * 32;
        float* r1 = out + (size_t)(b * COUT + o0 + 8) * HW + hw0 + wn * 32;
        #pragma unroll
        for (int j = 0; j < 4; j++) {
            float2 s0, s1;
            s0.x = acc[i][j][0] + bias0; s0.y = acc[i][j][1] + bias0;
            s1.x = acc[i][j][2] + bias1; s1.y = acc[i][j][3] + bias1;
            *(float2*)(r0 + j * 8 + t * 2) = s0;
            *(float2*)(r1 + j * 8 + t * 2) = s1;
        }
    }
}

// ---------------- launch -----------------------------------------------------
extern "C" void kernel_launch(void* const* d_in, const int* in_sizes, int n_in,
                              void* d_out, int out_size) {
    const float* x  = (const float*)d_in[0];
    const float* ow = (const float*)d_in[1];
    const float* ob = (const float*)d_in[2];
    const float* cw = (const float*)d_in[3];
    const float* cb = (const float*)d_in[4];
    float* out      = (float*)d_out;

    {
        dim3 grid(HW / 32, C_ / 32, B_);
        dim3 block(32, 8);
        k_transpose<<<grid, block>>>(x);
    }
    k_owt<<<(KDIM * 20 + 255) / 256, 256>>>(ow);
    k_wprep<<<(NCHUNK * 2 * 16 * 2 * 32) / 256, 256>>>(cw);
    k_offset<<<B_ * HW / 64, 256>>>(x, ob);

    // 2 M-tiles x (B_ * HW/128) pixel tiles = 400 blocks
    k_main<<<2 * B_ * (HW / 128), 256>>>(cb, out);
}

// round 5
// speedup vs baseline: 1.8992x; 1.0476x over previous
#include <cuda_runtime.h>
#include <cuda_bf16.h>
#include <cstdint>

#define B_    4
#define C_    256
#define H_    80
#define W_    80
#define HW    6400
#define K2    9
#define KDIM  2304
#define COUT  256
#define NCHUNK 72          // 9 taps * 8 channel-groups of 32

// ---------------- device scratch ----------------
__device__ float  g_xnhwc[B_ * HW * C_];          // x in NHWC
__device__ float  g_owT[KDIM * 20];               // offset weights transposed (18->20 pad)
__device__ uint4  g_wA[NCHUNK * 2 * 16 * 2 * 32]; // fragment-packed bf16 weights (hi/lo)
__device__ float4 g_twgt[B_ * K2 * HW];           // bilinear weights * validity
__device__ int4   g_tidx[B_ * K2 * HW];           // clamped NHWC bases

// ---------------- mma helpers ----------------
__device__ __forceinline__ void mma16816(float* d, const uint32_t* a, const uint32_t* b) {
    asm volatile(
        "mma.sync.aligned.m16n8k16.row.col.f32.bf16.bf16.f32 "
        "{%0,%1,%2,%3}, {%4,%5,%6,%7}, {%8,%9}, {%0,%1,%2,%3};"
        : "+f"(d[0]), "+f"(d[1]), "+f"(d[2]), "+f"(d[3])
        : "r"(a[0]), "r"(a[1]), "r"(a[2]), "r"(a[3]), "r"(b[0]), "r"(b[1]));
}

__device__ __forceinline__ void ldsm4(uint32_t* r, uint32_t addr) {
    asm volatile("ldmatrix.sync.aligned.m8n8.x4.shared.b16 {%0,%1,%2,%3}, [%4];"
                 : "=r"(r[0]), "=r"(r[1]), "=r"(r[2]), "=r"(r[3]) : "r"(addr));
}

__device__ __forceinline__ uint32_t pack_bf16(float lo_v, float hi_v) {
    __nv_bfloat162 h;
    h.x = __float2bfloat16(lo_v);
    h.y = __float2bfloat16(hi_v);
    return *(uint32_t*)&h;
}

// ---------------- kernel 1: NCHW -> NHWC transpose -------------------------
__global__ void k_transpose(const float* __restrict__ x) {
    __shared__ float tile[32][33];
    int b   = blockIdx.z;
    int hw0 = blockIdx.x * 32;
    int c0  = blockIdx.y * 32;
    int tx = threadIdx.x, ty = threadIdx.y;
    const float* xb = x + b * C_ * HW;
    #pragma unroll
    for (int i = 0; i < 32; i += 8)
        tile[ty + i][tx] = xb[(c0 + ty + i) * HW + hw0 + tx];
    __syncthreads();
    float* ob = g_xnhwc + b * HW * C_;
    #pragma unroll
    for (int i = 0; i < 32; i += 8)
        ob[(hw0 + ty + i) * C_ + c0 + tx] = tile[tx][ty + i];
}

// ---------------- kernel 2: offset-weight transpose ------------------------
__global__ void k_owt(const float* __restrict__ ow) {
    int idx = blockIdx.x * 256 + threadIdx.x;
    if (idx < KDIM * 20) {
        int row = idx / 20, oc = idx % 20;
        g_owT[idx] = (oc < 18) ? __ldg(ow + oc * KDIM + row) : 0.f;
    }
}

// ---------------- kernel 3: conv-weight split into mma fragment order ------
// g_wA index: ((((q*2 + term)*16 + mt)*2 + s)*32 + lane), each uint4 = the 4
// A-fragment regs for that lane of an m16n8k16 bf16 mma.
__global__ void k_wprep(const float* __restrict__ cw) {
    int e = blockIdx.x * 256 + threadIdx.x;
    if (e >= NCHUNK * 2 * 16 * 2 * 32) return;
    int lane = e & 31;
    int s    = (e >> 5) & 1;
    int mt   = (e >> 6) & 15;
    int term = (e >> 10) & 1;
    int q    = e >> 11;
    int tap   = q >> 3;
    int cbase = (q & 7) * 32;
    uint32_t r[4];
    #pragma unroll
    for (int rr = 0; rr < 4; rr++) {
        int m  = mt * 16 + (lane >> 2) + ((rr & 1) << 3);
        int kl = s * 16 + (lane & 3) * 2 + ((rr >> 1) << 3);
        float w0 = __ldg(cw + m * KDIM + (cbase + kl) * 9 + tap);
        float w1 = __ldg(cw + m * KDIM + (cbase + kl + 1) * 9 + tap);
        if (term) {
            w0 -= __bfloat162float(__float2bfloat16(w0));
            w1 -= __bfloat162float(__float2bfloat16(w1));
        }
        r[rr] = pack_bf16(w0, w1);
    }
    g_wA[e] = make_uint4(r[0], r[1], r[2], r[3]);
}

// ---------------- kernel 4: offset conv + tap metadata (R1 version) --------
__global__ void __launch_bounds__(256) k_offset(const float* __restrict__ x,
                                                const float* __restrict__ off_b) {
    __shared__ float red[8][32][18];
    __shared__ float offs[32][18];

    int pg   = blockIdx.x;                 // 0..799
    int b    = pg / (HW / 32);
    int hw0  = (pg % (HW / 32)) * 32;
    int lane = threadIdx.x & 31;
    int wq   = threadIdx.x >> 5;
    int p    = hw0 + lane;
    int py   = p / W_, px = p % W_;

    int noff[9];
    #pragma unroll
    for (int nb = 0; nb < 9; nb++) {
        int ny = py + nb / 3 - 1, nx = px + nb % 3 - 1;
        noff[nb] = (ny >= 0 && ny < H_ && nx >= 0 && nx < W_) ? ny * W_ + nx : -1;
    }

    float acc[18];
    #pragma unroll
    for (int i = 0; i < 18; i++) acc[i] = 0.f;

    int c0 = wq * 32;
    const float* xb = x + (size_t)(b * C_ + c0) * HW;
    for (int c = 0; c < 32; c++) {
        const float* xc = xb + c * HW;
        const float4* wr = (const float4*)(g_owT + (size_t)(c0 + c) * 180);
        #pragma unroll
        for (int nb = 0; nb < 9; nb++) {
            float xv = (noff[nb] >= 0) ? __ldg(xc + noff[nb]) : 0.f;
            const float4* w = wr + nb * 5;
            float wv[20];
            *(float4*)&wv[0]  = __ldg(w + 0);
            *(float4*)&wv[4]  = __ldg(w + 1);
            *(float4*)&wv[8]  = __ldg(w + 2);
            *(float4*)&wv[12] = __ldg(w + 3);
            *(float4*)&wv[16] = __ldg(w + 4);
            #pragma unroll
            for (int i = 0; i < 18; i++) acc[i] = fmaf(xv, wv[i], acc[i]);
        }
    }

    #pragma unroll
    for (int i = 0; i < 18; i++) red[wq][lane][i] = acc[i];
    __syncthreads();

    for (int u = threadIdx.x; u < 32 * 18; u += 256) {
        int l = u / 18, oc = u % 18;
        float s = 0.f;
        #pragma unroll
        for (int qx = 0; qx < 8; qx++) s += red[qx][l][oc];
        offs[l][oc] = s + __ldg(off_b + oc);
    }
    __syncthreads();

    for (int u = threadIdx.x; u < 32 * 9; u += 256) {
        int l = u / 9, k = u % 9;
        float dy = offs[l][2 * k], dx = offs[l][2 * k + 1];
        int pp = hw0 + l;
        int yy = pp / W_, xx = pp % W_;
        float fy = (float)(yy + k / 3 - 1) + dy;
        float fx = (float)(xx + k % 3 - 1) + dx;
        float y0f = floorf(fy), x0f = floorf(fx);
        float wy = fy - y0f, wx = fx - x0f;
        int y0 = (int)y0f, x0 = (int)x0f;
        int y1 = y0 + 1,   x1 = x0 + 1;
        float vy0 = (y0 >= 0 && y0 < H_) ? 1.f : 0.f;
        float vy1 = (y1 >= 0 && y1 < H_) ? 1.f : 0.f;
        float vx0 = (x0 >= 0 && x0 < W_) ? 1.f : 0.f;
        float vx1 = (x1 >= 0 && x1 < W_) ? 1.f : 0.f;
        int cy0 = min(max(y0, 0), H_ - 1), cy1 = min(max(y1, 0), H_ - 1);
        int cx0 = min(max(x0, 0), W_ - 1), cx1 = min(max(x1, 0), W_ - 1);
        float4 wt;
        wt.x = (1.f - wy) * (1.f - wx) * vy0 * vx0;
        wt.y = (1.f - wy) * wx         * vy0 * vx1;
        wt.z = wy * (1.f - wx)         * vy1 * vx0;
        wt.w = wy * wx                 * vy1 * vx1;
        int4 id;
        id.x = (cy0 * W_ + cx0) * C_;
        id.y = (cy0 * W_ + cx1) * C_;
        id.z = (cy1 * W_ + cx0) * C_;
        id.w = (cy1 * W_ + cx1) * C_;
        int m = (b * 9 + k) * HW + pp;
        g_twgt[m] = wt;
        g_tidx[m] = id;
    }
}

// ---------------- kernel 5: main GEMM via mma.sync bf16 split --------------
// Block: 128 M x 128 N, 256 threads (8 warps = 2 Mwarp x 4 Nwarp, warp tile
// 64x32). K = 2304 in 72 chunks of 32 (1 tap x 32 ch). B gathered+split into
// SMEM (80 B pixel stride); fragments read via conflict-free ldmatrix.x4.
// A loaded fragment-packed from global. 2 CTAs/SM alternate phases.
#define BROW 20    // u32 words per pixel row in sB

__global__ void __launch_bounds__(256, 2) k_main(const float* __restrict__ cb,
                                                 float* __restrict__ out) {
    __shared__ uint32_t sB[2][128 * BROW];   // [term][pixel*20 + word]

    int tid  = threadIdx.x;
    int wid  = tid >> 5, lane = tid & 31;
    int mb   = blockIdx.x & 1;
    int nblk = blockIdx.x >> 1;              // 0..199 (4 batches x 50 tiles)
    int b    = nblk / (HW / 128);
    int hw0  = (nblk % (HW / 128)) * 128;
    int wm   = wid >> 2, wn = wid & 3;

    float acc[4][4][4];
    #pragma unroll
    for (int i = 0; i < 4; i++)
        #pragma unroll
        for (int j = 0; j < 4; j++)
            #pragma unroll
            for (int r = 0; r < 4; r++) acc[i][j][r] = 0.f;

    const float4* xb4 = (const float4*)(g_xnhwc + (size_t)b * HW * C_);
    int b9 = b * 9;
    int p = tid >> 1, half = tid & 1;
    int mtbase = mb * 8 + wm * 4;

    // ldmatrix lane addresses (byte offsets into a term's sB plane).
    // x4 matrices: m0=(j=jb, k0-7), m1=(j=jb, k8-15), m2=(j=jb+1, k0-7), m3=(j=jb+1, k8-15)
    uint32_t sb0 = (uint32_t)__cvta_generic_to_shared(&sB[0][0]);
    uint32_t sb1 = (uint32_t)__cvta_generic_to_shared(&sB[1][0]);
    int mat = lane >> 3, mrow = lane & 7;
    int jd  = mat >> 1, kh = mat & 1;
    // offset within plane for (s, jb): ((wn*32 + (jb+jd)*8 + mrow)*BROW + s*8 + kh*4)*4
    uint32_t lm_base = ((wn * 32 + jd * 8 + mrow) * BROW + kh * 4) * 4;

    for (int q = 0; q < NCHUNK; q++) {
        int tap = q >> 3, cg = q & 7;
        int mm = (b9 + tap) * HW + hw0 + p;
        float4 wt = g_twgt[mm];
        int4  id  = g_tidx[mm];

        __syncthreads();   // previous chunk's mma done -> safe to overwrite sB

        #pragma unroll
        for (int qq = 0; qq < 4; qq++) {
            int c = cg * 32 + half * 16 + qq * 4;
            float4 t0 = __ldg(xb4 + ((id.x + c) >> 2));
            float4 t1 = __ldg(xb4 + ((id.y + c) >> 2));
            float4 t2 = __ldg(xb4 + ((id.z + c) >> 2));
            float4 t3 = __ldg(xb4 + ((id.w + c) >> 2));
            float4 v;
            v.x = wt.x * t0.x + wt.y * t1.x + wt.z * t2.x + wt.w * t3.x;
            v.y = wt.x * t0.y + wt.y * t1.y + wt.z * t2.y + wt.w * t3.y;
            v.z = wt.x * t0.z + wt.y * t1.z + wt.z * t2.z + wt.w * t3.z;
            v.w = wt.x * t0.w + wt.y * t1.w + wt.z * t2.w + wt.w * t3.w;
            uint32_t h01 = pack_bf16(v.x, v.y);
            uint32_t h23 = pack_bf16(v.z, v.w);
            __nv_bfloat162 hh01 = *(__nv_bfloat162*)&h01;
            __nv_bfloat162 hh23 = *(__nv_bfloat162*)&h23;
            float lx = v.x - __bfloat162float(hh01.x);
            float ly = v.y - __bfloat162float(hh01.y);
            float lz = v.z - __bfloat162float(hh23.x);
            float lw = v.w - __bfloat162float(hh23.y);
            uint32_t l01 = pack_bf16(lx, ly);
            uint32_t l23 = pack_bf16(lz, lw);
            int word = p * BROW + half * 8 + qq * 2;
            *(uint2*)&sB[0][word] = make_uint2(h01, h23);
            *(uint2*)&sB[1][word] = make_uint2(l01, l23);
        }
        __syncthreads();

        // ---- mma phase ----
        #pragma unroll
        for (int s = 0; s < 2; s++) {
            uint32_t soff = lm_base + (uint32_t)(s * 32);   // s*8 words
            uint32_t Bh[8], Bl[8];                          // [j][reg] flattened 2j+r
            ldsm4(Bh + 0, sb0 + soff);                      // j0,j1
            ldsm4(Bh + 4, sb0 + soff + (uint32_t)(16 * BROW * 4)); // j2,j3
            ldsm4(Bl + 0, sb1 + soff);
            ldsm4(Bl + 4, sb1 + soff + (uint32_t)(16 * BROW * 4));
            uint4 Ah[4];
            #pragma unroll
            for (int i = 0; i < 4; i++)
                Ah[i] = __ldg(&g_wA[(((q * 2 + 0) * 16 + mtbase + i) * 2 + s) * 32 + lane]);
            #pragma unroll
            for (int i = 0; i < 4; i++)
                #pragma unroll
                for (int j = 0; j < 4; j++)
                    mma16816(acc[i][j], (const uint32_t*)&Ah[i], Bh + 2 * j);
            #pragma unroll
            for (int i = 0; i < 4; i++)
                #pragma unroll
                for (int j = 0; j < 4; j++)
                    mma16816(acc[i][j], (const uint32_t*)&Ah[i], Bl + 2 * j);
            #pragma unroll
            for (int i = 0; i < 4; i++) {
                uint4 Al = __ldg(&g_wA[(((q * 2 + 1) * 16 + mtbase + i) * 2 + s) * 32 + lane]);
                #pragma unroll
                for (int j = 0; j < 4; j++)
                    mma16816(acc[i][j], (const uint32_t*)&Al, Bh + 2 * j);
            }
        }
    }

    // ---- epilogue: bias + NCHW store ----
    int q_ = lane >> 2, t = lane & 3;
    #pragma unroll
    for (int i = 0; i < 4; i++) {
        int o0 = mb * 128 + wm * 64 + i * 16 + q_;
        float bias0 = __ldg(cb + o0);
        float bias1 = __ldg(cb + o0 + 8);
        float* r0 = out + (size_t)(b * COUT + o0) * HW + hw0 + wn * 32;
        float* r1 = out + (size_t)(b * COUT + o0 + 8) * HW + hw0 + wn * 32;
        #pragma unroll
        for (int j = 0; j < 4; j++) {
            float2 s0, s1;
            s0.x = acc[i][j][0] + bias0; s0.y = acc[i][j][1] + bias0;
            s1.x = acc[i][j][2] + bias1; s1.y = acc[i][j][3] + bias1;
            *(float2*)(r0 + j * 8 + t * 2) = s0;
            *(float2*)(r1 + j * 8 + t * 2) = s1;
        }
    }
}

// ---------------- launch -----------------------------------------------------
extern "C" void kernel_launch(void* const* d_in, const int* in_sizes, int n_in,
                              void* d_out, int out_size) {
    const float* x  = (const float*)d_in[0];
    const float* ow = (const float*)d_in[1];
    const float* ob = (const float*)d_in[2];
    const float* cw = (const float*)d_in[3];
    const float* cb = (const float*)d_in[4];
    float* out      = (float*)d_out;

    {
        dim3 grid(HW / 32, C_ / 32, B_);
        dim3 block(32, 8);
        k_transpose<<<grid, block>>>(x);
    }
    k_owt<<<(KDIM * 20 + 255) / 256, 256>>>(ow);
    k_wprep<<<(NCHUNK * 2 * 16 * 2 * 32) / 256, 256>>>(cw);
    k_offset<<<B_ * HW / 32, 256>>>(x, ob);

    // 2 M-tiles x (B_ * HW/128) pixel tiles = 400 blocks
    k_main<<<2 * B_ * (HW / 128), 256>>>(cb, out);
}